// round 2
// baseline (speedup 1.0000x reference)
#include <cuda_runtime.h>
#include <cstdint>

// ---------------- problem constants ----------------
#define NB      32
#define NNODE   4096
#define NEDGE   16384
#define F1      16
#define F2      128
#define F3      256
#define KHEAD   (NNODE * F3)   // 1,048,576
#define NROWS   (NB * NNODE)   // 131072

// ---------------- scratch (device globals; no allocs allowed) ----------------
__device__ float g_a1[(size_t)NB * NNODE * F1];     // 8 MB  aggregated x
__device__ float g_h1[(size_t)NB * NNODE * F2];     // 64 MB relu(conv1)
__device__ float g_a2[(size_t)NB * NNODE * F2];     // 64 MB aggregated h1
__device__ float g_h2[(size_t)NB * NNODE * F3];     // 128 MB relu(conv2) == feat
__device__ float g_deg[NNODE];
__device__ float g_dinv[NNODE];
__device__ int   g_cnt[NNODE];
__device__ int   g_fill[NNODE];
__device__ int   g_rowptr[NNODE + 1];
__device__ int   g_col[NEDGE];
__device__ float g_nrm[NEDGE];
__device__ float g_P[NB * 80];                      // per-batch head partials (64 v1 | 12 adv | 4 pad)
__device__ int   g_is64;                            // edge_index dtype flag

// ---------------- edge read helper (int64 or int32 edge_index) ----------------
__device__ __forceinline__ void read_edge(const void* ei, int e, int& src, int& dst) {
    if (g_is64) {
        const long long* p = (const long long*)ei;
        src = (int)p[e]; dst = (int)p[NEDGE + e];
    } else {
        const int* p = (const int*)ei;
        src = p[e]; dst = p[NEDGE + e];
    }
}

// ---------------- K0: zero scratch + detect edge dtype ----------------
__global__ void zero_kernel(const int* __restrict__ ei32) {
    int i = blockIdx.x * blockDim.x + threadIdx.x;
    if (i < NNODE) { g_deg[i] = 0.f; g_cnt[i] = 0; g_fill[i] = 0; }
    if (i < NB * 80) g_P[i] = 0.f;
    if (i == 0) {
        // If data is int64, every odd 32-bit word of the first 256 entries is 0
        // (values are node ids < 4096). For int32 data these words are random ids.
        int any = 0;
        for (int k = 0; k < 256; k++) any |= ei32[2 * k + 1];
        g_is64 = (any == 0) ? 1 : 0;
    }
}

// ---------------- K1: degree + per-dst counts ----------------
__global__ void degcnt_kernel(const void* __restrict__ ei, const float* __restrict__ ew) {
    int e = blockIdx.x * blockDim.x + threadIdx.x;
    if (e >= NEDGE) return;
    int src, dst;
    read_edge(ei, e, src, dst);
    atomicAdd(&g_deg[dst], ew[e]);
    atomicAdd(&g_cnt[dst], 1);
}

// ---------------- K2: exclusive scan of counts (single block) + dinv_sqrt ----------------
__global__ __launch_bounds__(1024) void scan_kernel() {
    __shared__ int ss[1024];
    int t = threadIdx.x;
    int loc[4]; int s = 0;
#pragma unroll
    for (int i = 0; i < 4; i++) { loc[i] = s; s += g_cnt[4 * t + i]; }
    ss[t] = s;
    __syncthreads();
    int mysum = s;
    for (int off = 1; off < 1024; off <<= 1) {
        int v = (t >= off) ? ss[t - off] : 0;
        __syncthreads();
        ss[t] += v;
        __syncthreads();
    }
    int excl = ss[t] - mysum;
#pragma unroll
    for (int i = 0; i < 4; i++) {
        g_rowptr[4 * t + i] = excl + loc[i];
        g_dinv[4 * t + i] = rsqrtf(g_deg[4 * t + i] + 1.0f);
    }
    if (t == 1023) g_rowptr[NNODE] = ss[t];
}

// ---------------- K3: fill CSR (dst-sorted), compute edge norms ----------------
__global__ void fill_kernel(const void* __restrict__ ei, const float* __restrict__ ew) {
    int e = blockIdx.x * blockDim.x + threadIdx.x;
    if (e >= NEDGE) return;
    int src, dst;
    read_edge(ei, e, src, dst);
    int pos = g_rowptr[dst] + atomicAdd(&g_fill[dst], 1);
    g_col[pos] = src;
    g_nrm[pos] = ew[e] * g_dinv[src] * g_dinv[dst];
}

// ---------------- K4: aggregate x (F=16). block = node, 512 thr = 32 b x 16 f ----------------
__global__ __launch_bounds__(512) void agg16_kernel(const float* __restrict__ x) {
    int n = blockIdx.x;
    int tid = threadIdx.x;
    int b = tid >> 4, f = tid & 15;
    int beg = g_rowptr[n], end = g_rowptr[n + 1];
    float d = g_dinv[n];
    float d2 = d * d;
    const float* xb = x + (size_t)b * (NNODE * F1);
    float acc = d2 * xb[n * F1 + f];
    for (int j = beg; j < end; j++)
        acc = fmaf(g_nrm[j], xb[(size_t)g_col[j] * F1 + f], acc);
    g_a1[((size_t)b * NNODE + n) * F1 + f] = acc;
}

// ---------------- K5: h1 = relu(a1 @ W1 + b1). warp per row ----------------
__global__ __launch_bounds__(256) void gemm1_kernel(const float* __restrict__ W1, const float* __restrict__ b1) {
    __shared__ float Ws[16][128];
    __shared__ float bs[128];
    int tid = threadIdx.x;
    for (int id = tid; id < 16 * 128; id += 256) Ws[id >> 7][id & 127] = W1[id];
    if (tid < 128) bs[tid] = b1[tid];
    __syncthreads();
    int wid = tid >> 5, lane = tid & 31;
    size_t row = (size_t)blockIdx.x * 8 + wid;
    float av = (lane < 16) ? g_a1[row * F1 + lane] : 0.f;
    float acc[4] = {0.f, 0.f, 0.f, 0.f};
#pragma unroll
    for (int k = 0; k < 16; k++) {
        float a = __shfl_sync(0xffffffffu, av, k);
#pragma unroll
        for (int c = 0; c < 4; c++) acc[c] = fmaf(a, Ws[k][lane + 32 * c], acc[c]);
    }
#pragma unroll
    for (int c = 0; c < 4; c++)
        g_h1[row * F2 + lane + 32 * c] = fmaxf(acc[c] + bs[lane + 32 * c], 0.f);
}

// ---------------- K6: aggregate h1 (F=128). block = node, 512 thr, float4 x2 per thread -------
__global__ __launch_bounds__(512) void agg128_kernel() {
    int n = blockIdx.x;
    int tid = threadIdx.x;
    int b = tid >> 4, q = tid & 15;
    int beg = g_rowptr[n], end = g_rowptr[n + 1];
    float d = g_dinv[n];
    float d2 = d * d;
    const float4* hb = (const float4*)g_h1 + (size_t)b * (NNODE * 32);
    float4 s0 = hb[(size_t)n * 32 + q];
    float4 s1 = hb[(size_t)n * 32 + 16 + q];
    float4 a0 = make_float4(d2 * s0.x, d2 * s0.y, d2 * s0.z, d2 * s0.w);
    float4 a1 = make_float4(d2 * s1.x, d2 * s1.y, d2 * s1.z, d2 * s1.w);
    for (int j = beg; j < end; j++) {
        float w = g_nrm[j];
        size_t c = (size_t)g_col[j] * 32;
        float4 v0 = hb[c + q];
        float4 v1 = hb[c + 16 + q];
        a0.x = fmaf(w, v0.x, a0.x); a0.y = fmaf(w, v0.y, a0.y);
        a0.z = fmaf(w, v0.z, a0.z); a0.w = fmaf(w, v0.w, a0.w);
        a1.x = fmaf(w, v1.x, a1.x); a1.y = fmaf(w, v1.y, a1.y);
        a1.z = fmaf(w, v1.z, a1.z); a1.w = fmaf(w, v1.w, a1.w);
    }
    float4* ob = (float4*)g_a2 + (size_t)b * (NNODE * 32);
    ob[(size_t)n * 32 + q] = a0;
    ob[(size_t)n * 32 + 16 + q] = a1;
}

// ---------------- K7: h2 = relu(a2 @ W2 + b2). 128x128 tile, 8x8 per thread -------------------
__global__ __launch_bounds__(256) void gemm2_kernel(const float* __restrict__ W2, const float* __restrict__ b2) {
    __shared__ float As[8][128];
    __shared__ float Bs[8][128];
    int tid = threadIdx.x;
    int m0 = blockIdx.y * 128;
    int n0 = blockIdx.x * 128;
    int tm = (tid >> 4) * 8, tn = (tid & 15) * 8;
    float acc[8][8];
#pragma unroll
    for (int i = 0; i < 8; i++)
#pragma unroll
        for (int j = 0; j < 8; j++) acc[i][j] = 0.f;

    int arow = tid >> 1, acol = (tid & 1) * 4;
    int brow = tid >> 5, bcol = (tid & 31) * 4;
    const float* Abase = g_a2 + (size_t)(m0 + arow) * F2 + acol;
    const float* Bbase = W2 + (size_t)brow * F3 + n0 + bcol;

    for (int k0 = 0; k0 < F2; k0 += 8) {
        float4 avv = *(const float4*)(Abase + k0);
        float4 bvv = *(const float4*)(Bbase + (size_t)k0 * F3);
        As[acol + 0][arow] = avv.x;
        As[acol + 1][arow] = avv.y;
        As[acol + 2][arow] = avv.z;
        As[acol + 3][arow] = avv.w;
        *(float4*)&Bs[brow][bcol] = bvv;
        __syncthreads();
#pragma unroll
        for (int kk = 0; kk < 8; kk++) {
            float ra[8], rb[8];
            *(float4*)(ra)     = *(const float4*)&As[kk][tm];
            *(float4*)(ra + 4) = *(const float4*)&As[kk][tm + 4];
            *(float4*)(rb)     = *(const float4*)&Bs[kk][tn];
            *(float4*)(rb + 4) = *(const float4*)&Bs[kk][tn + 4];
#pragma unroll
            for (int i = 0; i < 8; i++)
#pragma unroll
                for (int j = 0; j < 8; j++)
                    acc[i][j] = fmaf(ra[i], rb[j], acc[i][j]);
        }
        __syncthreads();
    }
    float bb[8];
#pragma unroll
    for (int j = 0; j < 8; j++) bb[j] = b2[n0 + tn + j];
#pragma unroll
    for (int i = 0; i < 8; i++) {
        size_t r = (size_t)(m0 + tm + i);
        float o[8];
#pragma unroll
        for (int j = 0; j < 8; j++) o[j] = fmaxf(acc[i][j] + bb[j], 0.f);
        float* dst = &g_h2[r * F3 + n0 + tn];
        *(float4*)(dst)     = *(float4*)(o);
        *(float4*)(dst + 4) = *(float4*)(o + 4);
    }
}

// ---------------- K8: head partials P[b][0:64]=feat@v1W, P[b][64:76]=feat@advW ----------------
// grid 512 blocks, each owns K-slice of 2048; 160 threads = 5 warps; lane=batch, warp=j-block of 16.
__global__ __launch_bounds__(160) void head_kernel(const float* __restrict__ v1W, const float* __restrict__ advW) {
    const int TK = 64;
    __shared__ float sh_h[TK][33];
    __shared__ float sh_w[TK][80];
    int tid = threadIdx.x;
    int lane = tid & 31, wp = tid >> 5;   // wp in 0..4
    const int S = KHEAD / 512;            // 2048
    int k0 = blockIdx.x * S;
    float acc[16];
#pragma unroll
    for (int i = 0; i < 16; i++) acc[i] = 0.f;

    for (int t = 0; t < S; t += TK) {
        int kb = k0 + t;
        __syncthreads();
        for (int id = tid; id < NB * TK; id += 160) {
            int b = id >> 6, kk = id & 63;
            sh_h[kk][b] = g_h2[(size_t)b * KHEAD + kb + kk];
        }
        for (int id = tid; id < TK * 64; id += 160) {
            int kk = id >> 6, j = id & 63;
            sh_w[kk][j] = v1W[(size_t)(kb + kk) * 64 + j];
        }
        for (int id = tid; id < TK * 16; id += 160) {
            int kk = id >> 4, j = id & 15;
            sh_w[kk][64 + j] = (j < 12) ? advW[(size_t)(kb + kk) * 12 + j] : 0.f;
        }
        __syncthreads();
#pragma unroll 4
        for (int kk = 0; kk < TK; kk++) {
            float hd = sh_h[kk][lane];
            float4 w0 = *(const float4*)&sh_w[kk][wp * 16];
            float4 w1 = *(const float4*)&sh_w[kk][wp * 16 + 4];
            float4 w2 = *(const float4*)&sh_w[kk][wp * 16 + 8];
            float4 w3 = *(const float4*)&sh_w[kk][wp * 16 + 12];
            acc[0]  = fmaf(hd, w0.x, acc[0]);  acc[1]  = fmaf(hd, w0.y, acc[1]);
            acc[2]  = fmaf(hd, w0.z, acc[2]);  acc[3]  = fmaf(hd, w0.w, acc[3]);
            acc[4]  = fmaf(hd, w1.x, acc[4]);  acc[5]  = fmaf(hd, w1.y, acc[5]);
            acc[6]  = fmaf(hd, w1.z, acc[6]);  acc[7]  = fmaf(hd, w1.w, acc[7]);
            acc[8]  = fmaf(hd, w2.x, acc[8]);  acc[9]  = fmaf(hd, w2.y, acc[9]);
            acc[10] = fmaf(hd, w2.z, acc[10]); acc[11] = fmaf(hd, w2.w, acc[11]);
            acc[12] = fmaf(hd, w3.x, acc[12]); acc[13] = fmaf(hd, w3.y, acc[13]);
            acc[14] = fmaf(hd, w3.z, acc[14]); acc[15] = fmaf(hd, w3.w, acc[15]);
        }
    }
#pragma unroll
    for (int c = 0; c < 16; c++)
        atomicAdd(&g_P[lane * 80 + wp * 16 + c], acc[c]);
}

// ---------------- K9: finish heads: dueling combine ----------------
__global__ __launch_bounds__(256) void final_kernel(const float* __restrict__ advb, const float* __restrict__ v1b,
                             const float* __restrict__ v2W, const float* __restrict__ v2b,
                             const float* __restrict__ v3W, const float* __restrict__ v3b,
                             float* __restrict__ out) {
    __shared__ float sW[64 * 64];
    int tid = threadIdx.x;
    for (int id = tid; id < 64 * 64; id += 256) sW[id] = v2W[id];
    __syncthreads();
    int b = tid;
    if (b >= NB) return;
    float v1[64];
#pragma unroll
    for (int j = 0; j < 64; j++) v1[j] = fmaxf(g_P[b * 80 + j] + v1b[j], 0.f);
    float adv[12];
#pragma unroll
    for (int j = 0; j < 12; j++) adv[j] = fmaxf(g_P[b * 80 + 64 + j] + advb[j], 0.f);
    float val = v3b[0];
    for (int i = 0; i < 64; i++) {
        float a0 = 0.f, a1 = 0.f, a2 = 0.f, a3 = 0.f;
#pragma unroll
        for (int j = 0; j < 64; j += 4) {
            a0 = fmaf(v1[j],     sW[(j)     * 64 + i], a0);
            a1 = fmaf(v1[j + 1], sW[(j + 1) * 64 + i], a1);
            a2 = fmaf(v1[j + 2], sW[(j + 2) * 64 + i], a2);
            a3 = fmaf(v1[j + 3], sW[(j + 3) * 64 + i], a3);
        }
        float a = (a0 + a1) + (a2 + a3) + v2b[i];
        val = fmaf(fmaxf(a, 0.f), v3W[i], val);
    }
#pragma unroll
    for (int h = 0; h < 3; h++) {
        float m = 0.25f * (adv[4 * h] + adv[4 * h + 1] + adv[4 * h + 2] + adv[4 * h + 3]);
#pragma unroll
        for (int a = 0; a < 4; a++)
            out[b * 12 + h * 4 + a] = val + adv[4 * h + a] - m;
    }
}

// ---------------- launch ----------------
extern "C" void kernel_launch(void* const* d_in, const int* in_sizes, int n_in,
                              void* d_out, int out_size) {
    const float* x    = (const float*)d_in[0];
    const void*  ei   = d_in[1];
    const float* ew   = (const float*)d_in[2];
    const float* W1   = (const float*)d_in[3];
    const float* b1   = (const float*)d_in[4];
    const float* W2   = (const float*)d_in[5];
    const float* b2   = (const float*)d_in[6];
    const float* advW = (const float*)d_in[7];
    const float* advb = (const float*)d_in[8];
    const float* v1W  = (const float*)d_in[9];
    const float* v1b  = (const float*)d_in[10];
    const float* v2W  = (const float*)d_in[11];
    const float* v2b  = (const float*)d_in[12];
    const float* v3W  = (const float*)d_in[13];
    const float* v3b  = (const float*)d_in[14];
    float* out = (float*)d_out;

    zero_kernel<<<16, 256>>>((const int*)ei);
    degcnt_kernel<<<NEDGE / 256, 256>>>(ei, ew);
    scan_kernel<<<1, 1024>>>();
    fill_kernel<<<NEDGE / 256, 256>>>(ei, ew);
    agg16_kernel<<<NNODE, 512>>>(x);
    gemm1_kernel<<<NROWS / 8, 256>>>(W1, b1);
    agg128_kernel<<<NNODE, 512>>>();
    gemm2_kernel<<<dim3(2, NROWS / 128), 256>>>(W2, b2);
    head_kernel<<<512, 160>>>(v1W, advW);
    final_kernel<<<1, 256>>>(advb, v1b, v2W, v2b, v3W, v3b, out);
}

// round 4
// speedup vs baseline: 1.2254x; 1.2254x over previous
#include <cuda_runtime.h>
#include <cstdint>

// ---------------- problem constants ----------------
#define NB      32
#define NNODE   4096
#define NEDGE   16384
#define F1      16
#define F2      128
#define F3      256
#define KHEAD   (NNODE * F3)   // 1,048,576
#define NROWS   (NB * NNODE)   // 131072

// ---------------- scratch ----------------
__device__ float g_a1[(size_t)NB * NNODE * F1];
__device__ float g_h1[(size_t)NB * NNODE * F2];
__device__ float g_a2[(size_t)NB * NNODE * F2];
__device__ float g_h2[(size_t)NB * NNODE * F3];
__device__ float g_deg[NNODE];
__device__ float g_dinv[NNODE];
__device__ int   g_cnt[NNODE];
__device__ int   g_fill[NNODE];
__device__ int   g_rowptr[NNODE + 1];
__device__ int   g_col[NEDGE];
__device__ float g_nrm[NEDGE];
__device__ float g_P[NB * 80];
__device__ int   g_is64;

// ---------------- helpers ----------------
__device__ __forceinline__ float tf32r(float x) {
    float r;
    asm("cvt.rna.tf32.f32 %0, %1;" : "=f"(r) : "f"(x));
    return r;
}
// D += A(16x8 tf32) * B(8x8 tf32), f32 accum. Standard m16n8k8 fragments.
__device__ __forceinline__ void mma_tf32(float* d, const uint32_t* a, uint32_t b0, uint32_t b1) {
    asm volatile(
        "mma.sync.aligned.m16n8k8.row.col.f32.tf32.tf32.f32 "
        "{%0,%1,%2,%3}, {%4,%5,%6,%7}, {%8,%9}, {%0,%1,%2,%3};"
        : "+f"(d[0]), "+f"(d[1]), "+f"(d[2]), "+f"(d[3])
        : "r"(a[0]), "r"(a[1]), "r"(a[2]), "r"(a[3]), "r"(b0), "r"(b1));
}

// ---------------- edge read helper ----------------
__device__ __forceinline__ void read_edge(const void* ei, int e, int& src, int& dst) {
    if (g_is64) {
        const long long* p = (const long long*)ei;
        src = (int)p[e]; dst = (int)p[NEDGE + e];
    } else {
        const int* p = (const int*)ei;
        src = p[e]; dst = p[NEDGE + e];
    }
}

// ---------------- K0 ----------------
__global__ void zero_kernel(const int* __restrict__ ei32) {
    int i = blockIdx.x * blockDim.x + threadIdx.x;
    if (i < NNODE) { g_deg[i] = 0.f; g_cnt[i] = 0; g_fill[i] = 0; }
    if (i < NB * 80) g_P[i] = 0.f;
    if (i == 0) {
        int any = 0;
        for (int k = 0; k < 256; k++) any |= ei32[2 * k + 1];
        g_is64 = (any == 0) ? 1 : 0;
    }
}

// ---------------- K1 ----------------
__global__ void degcnt_kernel(const void* __restrict__ ei, const float* __restrict__ ew) {
    int e = blockIdx.x * blockDim.x + threadIdx.x;
    if (e >= NEDGE) return;
    int src, dst;
    read_edge(ei, e, src, dst);
    atomicAdd(&g_deg[dst], ew[e]);
    atomicAdd(&g_cnt[dst], 1);
}

// ---------------- K2 ----------------
__global__ __launch_bounds__(1024) void scan_kernel() {
    __shared__ int ss[1024];
    int t = threadIdx.x;
    int loc[4]; int s = 0;
#pragma unroll
    for (int i = 0; i < 4; i++) { loc[i] = s; s += g_cnt[4 * t + i]; }
    ss[t] = s;
    __syncthreads();
    int mysum = s;
    for (int off = 1; off < 1024; off <<= 1) {
        int v = (t >= off) ? ss[t - off] : 0;
        __syncthreads();
        ss[t] += v;
        __syncthreads();
    }
    int excl = ss[t] - mysum;
#pragma unroll
    for (int i = 0; i < 4; i++) {
        g_rowptr[4 * t + i] = excl + loc[i];
        g_dinv[4 * t + i] = rsqrtf(g_deg[4 * t + i] + 1.0f);
    }
    if (t == 1023) g_rowptr[NNODE] = ss[t];
}

// ---------------- K3 ----------------
__global__ void fill_kernel(const void* __restrict__ ei, const float* __restrict__ ew) {
    int e = blockIdx.x * blockDim.x + threadIdx.x;
    if (e >= NEDGE) return;
    int src, dst;
    read_edge(ei, e, src, dst);
    int pos = g_rowptr[dst] + atomicAdd(&g_fill[dst], 1);
    g_col[pos] = src;
    g_nrm[pos] = ew[e] * g_dinv[src] * g_dinv[dst];
}

// ---------------- K4: aggregate x (F=16) ----------------
__global__ __launch_bounds__(512) void agg16_kernel(const float* __restrict__ x) {
    int n = blockIdx.x;
    int tid = threadIdx.x;
    int b = tid >> 4, f = tid & 15;
    int beg = g_rowptr[n], end = g_rowptr[n + 1];
    float d = g_dinv[n];
    float d2 = d * d;
    const float* xb = x + (size_t)b * (NNODE * F1);
    float acc = d2 * xb[n * F1 + f];
    for (int j = beg; j < end; j++)
        acc = fmaf(g_nrm[j], xb[(size_t)g_col[j] * F1 + f], acc);
    g_a1[((size_t)b * NNODE + n) * F1 + f] = acc;
}

// ---------------- K5: gemm1 ----------------
__global__ __launch_bounds__(256) void gemm1_kernel(const float* __restrict__ W1, const float* __restrict__ b1) {
    __shared__ float Ws[16][128];
    __shared__ float bs[128];
    int tid = threadIdx.x;
    for (int id = tid; id < 16 * 128; id += 256) Ws[id >> 7][id & 127] = W1[id];
    if (tid < 128) bs[tid] = b1[tid];
    __syncthreads();
    int wid = tid >> 5, lane = tid & 31;
    size_t row = (size_t)blockIdx.x * 8 + wid;
    float av = (lane < 16) ? g_a1[row * F1 + lane] : 0.f;
    float acc[4] = {0.f, 0.f, 0.f, 0.f};
#pragma unroll
    for (int k = 0; k < 16; k++) {
        float a = __shfl_sync(0xffffffffu, av, k);
#pragma unroll
        for (int c = 0; c < 4; c++) acc[c] = fmaf(a, Ws[k][lane + 32 * c], acc[c]);
    }
#pragma unroll
    for (int c = 0; c < 4; c++)
        g_h1[row * F2 + lane + 32 * c] = fmaxf(acc[c] + bs[lane + 32 * c], 0.f);
}

// ---------------- K6: aggregate h1 (F=128) ----------------
__global__ __launch_bounds__(512) void agg128_kernel() {
    int n = blockIdx.x;
    int tid = threadIdx.x;
    int b = tid >> 4, q = tid & 15;
    int beg = g_rowptr[n], end = g_rowptr[n + 1];
    float d = g_dinv[n];
    float d2 = d * d;
    const float4* hb = (const float4*)g_h1 + (size_t)b * (NNODE * 32);
    float4 s0 = hb[(size_t)n * 32 + q];
    float4 s1 = hb[(size_t)n * 32 + 16 + q];
    float4 a0 = make_float4(d2 * s0.x, d2 * s0.y, d2 * s0.z, d2 * s0.w);
    float4 a1 = make_float4(d2 * s1.x, d2 * s1.y, d2 * s1.z, d2 * s1.w);
    for (int j = beg; j < end; j++) {
        float w = g_nrm[j];
        size_t c = (size_t)g_col[j] * 32;
        float4 v0 = hb[c + q];
        float4 v1 = hb[c + 16 + q];
        a0.x = fmaf(w, v0.x, a0.x); a0.y = fmaf(w, v0.y, a0.y);
        a0.z = fmaf(w, v0.z, a0.z); a0.w = fmaf(w, v0.w, a0.w);
        a1.x = fmaf(w, v1.x, a1.x); a1.y = fmaf(w, v1.y, a1.y);
        a1.z = fmaf(w, v1.z, a1.z); a1.w = fmaf(w, v1.w, a1.w);
    }
    float4* ob = (float4*)g_a2 + (size_t)b * (NNODE * 32);
    ob[(size_t)n * 32 + q] = a0;
    ob[(size_t)n * 32 + 16 + q] = a1;
}

// ---------------- K7: gemm2 via mma.sync tf32 (3xTF32) ----------------
// Block tile 128(M) x 128(N), K-chunks of 32. 256 threads = 8 warps (2 M x 4 N),
// warp tile 64x32 -> 4 m-tiles x 4 n-tiles of m16n8k8.
// dyn smem (floats): Ah[128][36] | Al[128][36] | Bh[32][136] | Bl[32][136]
#define G2_AH   0
#define G2_AL   (128 * 36)
#define G2_BH   (2 * 128 * 36)
#define G2_BB   (32 * 136)
#define G2_SMEM ((2 * 128 * 36 + 2 * 32 * 136) * 4)

__global__ __launch_bounds__(256) void gemm2_mma_kernel(const float* __restrict__ W2,
                                                        const float* __restrict__ b2) {
    extern __shared__ float sm[];
    float* Ah = sm + G2_AH;
    float* Al = sm + G2_AL;
    float* Bh = sm + G2_BH;
    float* Bl = sm + G2_BH + G2_BB;
    const uint32_t* uAh = (const uint32_t*)Ah;
    const uint32_t* uAl = (const uint32_t*)Al;
    const uint32_t* uBh = (const uint32_t*)Bh;
    const uint32_t* uBl = (const uint32_t*)Bl;

    int tid = threadIdx.x;
    int wid = tid >> 5, lane = tid & 31;
    int gid = lane >> 2, tig = lane & 3;
    int wm = wid & 1, wn = wid >> 1;          // 2 x 4 warp grid
    int m0 = blockIdx.y * 128;
    int n0 = blockIdx.x * 128;

    float acc[4][4][4];
#pragma unroll
    for (int i = 0; i < 4; i++)
#pragma unroll
        for (int j = 0; j < 4; j++)
#pragma unroll
            for (int r = 0; r < 4; r++) acc[i][j][r] = 0.f;

    for (int c = 0; c < 4; c++) {
        int k0 = c * 32;
        if (c) __syncthreads();
        // A: 128 rows x 32 k  (hi/lo), layout [m][36]
#pragma unroll
        for (int i = 0; i < 4; i++) {
            int idx = tid + i * 256;              // 0..1023 float4 slots
            int m = idx >> 3, kq = idx & 7;
            float4 v = ((const float4*)(g_a2 + (size_t)(m0 + m) * F2 + k0))[kq];
            float4 hi, lo;
            hi.x = tf32r(v.x); lo.x = tf32r(v.x - hi.x);
            hi.y = tf32r(v.y); lo.y = tf32r(v.y - hi.y);
            hi.z = tf32r(v.z); lo.z = tf32r(v.z - hi.z);
            hi.w = tf32r(v.w); lo.w = tf32r(v.w - hi.w);
            *(float4*)(Ah + m * 36 + kq * 4) = hi;
            *(float4*)(Al + m * 36 + kq * 4) = lo;
        }
        // B: 32 k-rows x 128 n  (hi/lo), layout [k][136]
#pragma unroll
        for (int i = 0; i < 4; i++) {
            int idx = tid + i * 256;              // 0..1023 float4 slots
            int k = idx >> 5, nq = idx & 31;
            float4 v = ((const float4*)(W2 + (size_t)(k0 + k) * F3 + n0))[nq];
            float4 hi, lo;
            hi.x = tf32r(v.x); lo.x = tf32r(v.x - hi.x);
            hi.y = tf32r(v.y); lo.y = tf32r(v.y - hi.y);
            hi.z = tf32r(v.z); lo.z = tf32r(v.z - hi.z);
            hi.w = tf32r(v.w); lo.w = tf32r(v.w - hi.w);
            *(float4*)(Bh + k * 136 + nq * 4) = hi;
            *(float4*)(Bl + k * 136 + nq * 4) = lo;
        }
        __syncthreads();

#pragma unroll
        for (int ks = 0; ks < 4; ks++) {
            int kc = ks * 8;
            uint32_t ah[4][4], al[4][4];
#pragma unroll
            for (int mt = 0; mt < 4; mt++) {
                int r = wm * 64 + mt * 16 + gid;
                ah[mt][0] = uAh[r * 36 + kc + tig];
                ah[mt][1] = uAh[(r + 8) * 36 + kc + tig];
                ah[mt][2] = uAh[r * 36 + kc + tig + 4];
                ah[mt][3] = uAh[(r + 8) * 36 + kc + tig + 4];
                al[mt][0] = uAl[r * 36 + kc + tig];
                al[mt][1] = uAl[(r + 8) * 36 + kc + tig];
                al[mt][2] = uAl[r * 36 + kc + tig + 4];
                al[mt][3] = uAl[(r + 8) * 36 + kc + tig + 4];
            }
#pragma unroll
            for (int nt = 0; nt < 4; nt++) {
                int ncol = wn * 32 + nt * 8 + gid;
                uint32_t bh0 = uBh[(kc + tig) * 136 + ncol];
                uint32_t bh1 = uBh[(kc + tig + 4) * 136 + ncol];
                uint32_t bl0 = uBl[(kc + tig) * 136 + ncol];
                uint32_t bl1 = uBl[(kc + tig + 4) * 136 + ncol];
#pragma unroll
                for (int mt = 0; mt < 4; mt++) {
                    mma_tf32(acc[mt][nt], ah[mt], bh0, bh1);
                    mma_tf32(acc[mt][nt], al[mt], bh0, bh1);
                    mma_tf32(acc[mt][nt], ah[mt], bl0, bl1);
                }
            }
        }
    }

    // epilogue: bias + relu + store
#pragma unroll
    for (int mt = 0; mt < 4; mt++) {
        int r = m0 + wm * 64 + mt * 16 + gid;
#pragma unroll
        for (int nt = 0; nt < 4; nt++) {
            int ccol = n0 + wn * 32 + nt * 8 + tig * 2;
            float bb0 = __ldg(b2 + ccol), bb1 = __ldg(b2 + ccol + 1);
            float2 v0 = make_float2(fmaxf(acc[mt][nt][0] + bb0, 0.f),
                                    fmaxf(acc[mt][nt][1] + bb1, 0.f));
            float2 v1 = make_float2(fmaxf(acc[mt][nt][2] + bb0, 0.f),
                                    fmaxf(acc[mt][nt][3] + bb1, 0.f));
            *(float2*)(g_h2 + (size_t)r * F3 + ccol) = v0;
            *(float2*)(g_h2 + (size_t)(r + 8) * F3 + ccol) = v1;
        }
    }
}

// ---------------- K8: head via mma.sync tf32 (3xTF32) ----------------
// P[32 x 80] = feat[32 x 1M] @ [v1W | advW | 0pad][1M x 80].
// 1024 blocks x K-slice 1024. 256 thr = 8 warps; chunk TK=64 k; warp w handles
// k-substep w*8..w*8+7 of each chunk. m-tiles 2 (M=32), n-tiles 10 (N=80).
#define HGB    1024
#define H_AH   0
#define H_AL   (32 * 68)
#define H_WH   (2 * 32 * 68)
#define H_WB   (64 * 88)
#define H_SP   (H_WH + 2 * H_WB)
#define H_SMEM ((H_SP + 2560) * 4)

__global__ __launch_bounds__(256) void head_mma_kernel(const float* __restrict__ v1W,
                                                       const float* __restrict__ advW) {
    extern __shared__ float sm[];
    float* Ah = sm + H_AH;
    float* Al = sm + H_AL;
    float* Wh = sm + H_WH;
    float* Wl = sm + H_WH + H_WB;
    float* sP = sm + H_SP;
    const uint32_t* uAh = (const uint32_t*)Ah;
    const uint32_t* uAl = (const uint32_t*)Al;
    const uint32_t* uWh = (const uint32_t*)Wh;
    const uint32_t* uWl = (const uint32_t*)Wl;

    int tid = threadIdx.x;
    int wid = tid >> 5, lane = tid & 31;
    int gid = lane >> 2, tig = lane & 3;

    for (int i = tid; i < 2560; i += 256) sP[i] = 0.f;

    float acc[2][10][4];
#pragma unroll
    for (int i = 0; i < 2; i++)
#pragma unroll
        for (int j = 0; j < 10; j++)
#pragma unroll
            for (int r = 0; r < 4; r++) acc[i][j][r] = 0.f;

    for (int ch = 0; ch < 16; ch++) {
        int k0 = blockIdx.x * 1024 + ch * 64;
        __syncthreads();
        // feat: 32 b x 64 k  -> Ah[32][68]
#pragma unroll
        for (int i = 0; i < 8; i++) {
            int idx = tid + i * 256;              // 0..2047
            int b = idx >> 6, kk = idx & 63;
            float v = g_h2[(size_t)b * KHEAD + k0 + kk];
            float hi = tf32r(v), lo = tf32r(v - hi);
            Ah[b * 68 + kk] = hi;
            Al[b * 68 + kk] = lo;
        }
        // v1W: 64 k x 64 j -> Wh[64][88] cols 0..63
#pragma unroll
        for (int i = 0; i < 16; i++) {
            int idx = tid + i * 256;              // 0..4095
            int kk = idx >> 6, j = idx & 63;
            float w = v1W[(size_t)(k0 + kk) * 64 + j];
            float hi = tf32r(w), lo = tf32r(w - hi);
            Wh[kk * 88 + j] = hi;
            Wl[kk * 88 + j] = lo;
        }
        // advW: 64 k x 12 j -> cols 64..75
        for (int i = tid; i < 768; i += 256) {
            int kk = i / 12, j = i - kk * 12;
            float w = advW[(size_t)(k0 + kk) * 12 + j];
            float hi = tf32r(w), lo = tf32r(w - hi);
            Wh[kk * 88 + 64 + j] = hi;
            Wl[kk * 88 + 64 + j] = lo;
        }
        // pad cols 76..79 with zeros
        {
            int kk = tid >> 2, j = 76 + (tid & 3);
            if (kk < 64) { Wh[kk * 88 + j] = 0.f; Wl[kk * 88 + j] = 0.f; }
        }
        __syncthreads();

        int kc = wid * 8;                         // this warp's k-substep
        uint32_t ah[2][4], al[2][4];
#pragma unroll
        for (int mt = 0; mt < 2; mt++) {
            int b = mt * 16 + gid;
            ah[mt][0] = uAh[b * 68 + kc + tig];
            ah[mt][1] = uAh[(b + 8) * 68 + kc + tig];
            ah[mt][2] = uAh[b * 68 + kc + tig + 4];
            ah[mt][3] = uAh[(b + 8) * 68 + kc + tig + 4];
            al[mt][0] = uAl[b * 68 + kc + tig];
            al[mt][1] = uAl[(b + 8) * 68 + kc + tig];
            al[mt][2] = uAl[b * 68 + kc + tig + 4];
            al[mt][3] = uAl[(b + 8) * 68 + kc + tig + 4];
        }
#pragma unroll
        for (int nt = 0; nt < 10; nt++) {
            int ncol = nt * 8 + gid;
            uint32_t bh0 = uWh[(kc + tig) * 88 + ncol];
            uint32_t bh1 = uWh[(kc + tig + 4) * 88 + ncol];
            uint32_t bl0 = uWl[(kc + tig) * 88 + ncol];
            uint32_t bl1 = uWl[(kc + tig + 4) * 88 + ncol];
#pragma unroll
            for (int mt = 0; mt < 2; mt++) {
                mma_tf32(acc[mt][nt], ah[mt], bh0, bh1);
                mma_tf32(acc[mt][nt], al[mt], bh0, bh1);
                mma_tf32(acc[mt][nt], ah[mt], bl0, bl1);
            }
        }
    }

    // reduce 8 warps into sP, then global atomics
#pragma unroll
    for (int mt = 0; mt < 2; mt++) {
        int b = mt * 16 + gid;
#pragma unroll
        for (int nt = 0; nt < 10; nt++) {
            int j = nt * 8 + tig * 2;
            atomicAdd(&sP[b * 80 + j],           acc[mt][nt][0]);
            atomicAdd(&sP[b * 80 + j + 1],       acc[mt][nt][1]);
            atomicAdd(&sP[(b + 8) * 80 + j],     acc[mt][nt][2]);
            atomicAdd(&sP[(b + 8) * 80 + j + 1], acc[mt][nt][3]);
        }
    }
    __syncthreads();
    for (int i = tid; i < 2560; i += 256)
        atomicAdd(&g_P[i], sP[i]);
}

// ---------------- K9: finish heads ----------------
__global__ __launch_bounds__(256) void final_kernel(const float* __restrict__ advb, const float* __restrict__ v1b,
                             const float* __restrict__ v2W, const float* __restrict__ v2b,
                             const float* __restrict__ v3W, const float* __restrict__ v3b,
                             float* __restrict__ out) {
    __shared__ float sW[64 * 64];
    int tid = threadIdx.x;
    for (int id = tid; id < 64 * 64; id += 256) sW[id] = v2W[id];
    __syncthreads();
    int b = tid;
    if (b >= NB) return;
    float v1[64];
#pragma unroll
    for (int j = 0; j < 64; j++) v1[j] = fmaxf(g_P[b * 80 + j] + v1b[j], 0.f);
    float adv[12];
#pragma unroll
    for (int j = 0; j < 12; j++) adv[j] = fmaxf(g_P[b * 80 + 64 + j] + advb[j], 0.f);
    float val = v3b[0];
    for (int i = 0; i < 64; i++) {
        float a0 = 0.f, a1 = 0.f, a2 = 0.f, a3 = 0.f;
#pragma unroll
        for (int j = 0; j < 64; j += 4) {
            a0 = fmaf(v1[j],     sW[(j)     * 64 + i], a0);
            a1 = fmaf(v1[j + 1], sW[(j + 1) * 64 + i], a1);
            a2 = fmaf(v1[j + 2], sW[(j + 2) * 64 + i], a2);
            a3 = fmaf(v1[j + 3], sW[(j + 3) * 64 + i], a3);
        }
        float a = (a0 + a1) + (a2 + a3) + v2b[i];
        val = fmaf(fmaxf(a, 0.f), v3W[i], val);
    }
#pragma unroll
    for (int h = 0; h < 3; h++) {
        float m = 0.25f * (adv[4 * h] + adv[4 * h + 1] + adv[4 * h + 2] + adv[4 * h + 3]);
#pragma unroll
        for (int a = 0; a < 4; a++)
            out[b * 12 + h * 4 + a] = val + adv[4 * h + a] - m;
    }
}

// ---------------- launch ----------------
extern "C" void kernel_launch(void* const* d_in, const int* in_sizes, int n_in,
                              void* d_out, int out_size) {
    const float* x    = (const float*)d_in[0];
    const void*  ei   = d_in[1];
    const float* ew   = (const float*)d_in[2];
    const float* W1   = (const float*)d_in[3];
    const float* b1   = (const float*)d_in[4];
    const float* W2   = (const float*)d_in[5];
    const float* b2   = (const float*)d_in[6];
    const float* advW = (const float*)d_in[7];
    const float* advb = (const float*)d_in[8];
    const float* v1W  = (const float*)d_in[9];
    const float* v1b  = (const float*)d_in[10];
    const float* v2W  = (const float*)d_in[11];
    const float* v2b  = (const float*)d_in[12];
    const float* v3W  = (const float*)d_in[13];
    const float* v3b  = (const float*)d_in[14];
    float* out = (float*)d_out;

    static int attr_done = 0;
    if (!attr_done) {
        cudaFuncSetAttribute(gemm2_mma_kernel, cudaFuncAttributeMaxDynamicSharedMemorySize, G2_SMEM);
        cudaFuncSetAttribute(head_mma_kernel,  cudaFuncAttributeMaxDynamicSharedMemorySize, H_SMEM);
        attr_done = 1;
    }

    zero_kernel<<<16, 256>>>((const int*)ei);
    degcnt_kernel<<<NEDGE / 256, 256>>>(ei, ew);
    scan_kernel<<<1, 1024>>>();
    fill_kernel<<<NEDGE / 256, 256>>>(ei, ew);
    agg16_kernel<<<NNODE, 512>>>(x);
    gemm1_kernel<<<NROWS / 8, 256>>>(W1, b1);
    agg128_kernel<<<NNODE, 512>>>();
    gemm2_mma_kernel<<<dim3(2, NROWS / 128), 256, G2_SMEM>>>(W2, b2);
    head_mma_kernel<<<HGB, 256, H_SMEM>>>(v1W, advW);
    final_kernel<<<1, 256>>>(advb, v1b, v2W, v2b, v3W, v3b, out);
}